// round 1
// baseline (speedup 1.0000x reference)
#include <cuda_runtime.h>

#define NJ   17
#define NP   14
#define NB   256
#define NCH  59   // 17 + 3*14

__constant__ int c_par[NP] = {0,1,2,0,4,5,0,8,14,15,8,11,12,8};
__constant__ int c_chi[NP] = {1,2,3,4,5,6,8,14,15,16,11,12,13,10};

// accumulators: [0]=l3d_sum, [1]=L2D_sum, [2]=LHEM_sum
__device__ double g_acc[3];

// Block-wide sum over 256 threads. Result valid on thread 0.
__device__ __forceinline__ float blockReduce(float v, float* shm) {
    __syncthreads();  // protect shm reuse across consecutive reductions
    #pragma unroll
    for (int o = 16; o > 0; o >>= 1) v += __shfl_down_sync(0xffffffffu, v, o);
    if ((threadIdx.x & 31) == 0) shm[threadIdx.x >> 5] = v;
    __syncthreads();
    v = (threadIdx.x < 8) ? shm[threadIdx.x] : 0.f;
    if (threadIdx.x < 32) {
        #pragma unroll
        for (int o = 4; o > 0; o >>= 1) v += __shfl_down_sync(0xffffffffu, v, o);
    }
    return v;
}

// Kernel 1: zero accumulators + compute l3d sum. One block of 256 threads,
// thread b handles batch b.
__global__ void k_init_l3d(const float* __restrict__ pred,
                           const float* __restrict__ joints) {
    __shared__ float shm[8];
    int b = threadIdx.x;
    if (b < 3) g_acc[b] = 0.0;
    float s = 0.f;
    #pragma unroll
    for (int i = 0; i < NJ * 3; i++)
        s += fabsf(joints[b * NJ * 3 + i] - pred[b * NJ * 3 + i]);
    float tot = blockReduce(s, shm);
    if (threadIdx.x == 0) g_acc[0] = (double)tot;
}

// Kernel 2: fused streaming pass over middle_out.
// blockIdx.y = batch b.  blockIdx.x in [0,17): L2D for joint j.
//                        blockIdx.x in [17,31): HEM for pair (x-17).
__global__ void __launch_bounds__(256)
k_main(const float* __restrict__ mo,
       const float* __restrict__ joints,
       const float* __restrict__ j2d) {
    __shared__ float ex[64], ey[64], ex2[64], ey2[64];
    __shared__ float sinv[2];
    __shared__ float red[8];

    const int b   = blockIdx.y;
    const int tid = threadIdx.x;

    if (blockIdx.x < NJ) {
        // ---------------- L2D path ----------------
        const int j = blockIdx.x;
        const float x = j2d[(b * NJ + j) * 2 + 0] * 64.f;
        const float y = j2d[(b * NJ + j) * 2 + 1] * 64.f;
        if (tid < 64)       { float d = (float)tid        - x; ex[tid]      = expf(-d * d * 0.25f); }
        else if (tid < 128) { int k = tid - 64; float d = (float)k - y; ey[k] = expf(-d * d * 0.25f); }
        __syncthreads();
        if (tid == 0) {
            float mx = ex[0], my = ey[0];
            #pragma unroll
            for (int i = 1; i < 64; i++) { mx = fmaxf(mx, ex[i]); my = fmaxf(my, ey[i]); }
            sinv[0] = 1.f / (mx * my);
        }
        __syncthreads();
        const float inv = sinv[0];
        const float4* p = (const float4*)(mo + (((size_t)b * NCH + j) << 12));
        float acc = 0.f;
        #pragma unroll
        for (int it = 0; it < 4; it++) {
            int e4 = tid + it * 256;
            float4 m = p[e4];
            int e = e4 << 2;
            int i = e >> 6, k = e & 63;
            float hx = ex[i] * inv;
            float d0 = m.x - hx * ey[k + 0];
            float d1 = m.y - hx * ey[k + 1];
            float d2 = m.z - hx * ey[k + 2];
            float d3 = m.w - hx * ey[k + 3];
            acc += d0 * d0 + d1 * d1 + d2 * d2 + d3 * d3;
        }
        float tot = blockReduce(acc, red);
        if (tid == 0) atomicAdd(&g_acc[1], (double)tot);
    } else {
        // ---------------- HEM path ----------------
        const int pr = blockIdx.x - NJ;
        const int pj = c_par[pr], cj = c_chi[pr];
        const float xp = j2d[(b * NJ + pj) * 2 + 0] * 64.f;
        const float yp = j2d[(b * NJ + pj) * 2 + 1] * 64.f;
        const float xc = j2d[(b * NJ + cj) * 2 + 0] * 64.f;
        const float yc = j2d[(b * NJ + cj) * 2 + 1] * 64.f;
        if (tid < 64)       { float d = (float)tid         - xp; ex [tid]       = expf(-d * d * 0.25f); }
        else if (tid < 128) { int k = tid - 64;  float d = (float)k - yp; ey [k] = expf(-d * d * 0.25f); }
        else if (tid < 192) { int k = tid - 128; float d = (float)k - xc; ex2[k] = expf(-d * d * 0.25f); }
        else                { int k = tid - 192; float d = (float)k - yc; ey2[k] = expf(-d * d * 0.25f); }
        __syncthreads();
        if (tid == 0) {
            float mx = ex[0], my = ey[0];
            #pragma unroll
            for (int i = 1; i < 64; i++) { mx = fmaxf(mx, ex[i]); my = fmaxf(my, ey[i]); }
            sinv[0] = 1.f / (mx * my);
        }
        if (tid == 32) {
            float mx = ex2[0], my = ey2[0];
            #pragma unroll
            for (int i = 1; i < 64; i++) { mx = fmaxf(mx, ex2[i]); my = fmaxf(my, ey2[i]); }
            sinv[1] = 1.f / (mx * my);
        }
        __syncthreads();
        const float invp = sinv[0], invc = sinv[1];

        const float dz = joints[(b * NJ + pj) * 3 + 2] - joints[(b * NJ + cj) * 3 + 2];
        const int r = (dz > 0.1f) ? 1 : ((fabsf(dz) < 0.1f) ? 0 : -1);

        const float4* p0 = (const float4*)(mo + (((size_t)b * NCH + NJ + pr * 3) << 12));
        float a0 = 0.f, a1 = 0.f, a2 = 0.f;
        #pragma unroll
        for (int it = 0; it < 4; it++) {
            int e4 = tid + it * 256;
            int e  = e4 << 2;
            int i  = e >> 6, k = e & 63;
            float hpx = ex[i]  * invp;
            float hcx = ex2[i] * invc;
            float m0[4], m1[4], m2[4];
            *(float4*)m0 = p0[e4];
            *(float4*)m1 = p0[e4 + 1024];
            *(float4*)m2 = p0[e4 + 2048];
            #pragma unroll
            for (int n = 0; n < 4; n++) {
                float hp = hpx * ey[k + n];
                float hc = hcx * ey2[k + n];
                float t0 = (r == -1) ? hc : 0.f;
                float t1 = (r ==  0) ? (hp + hc) : hp;
                float t2 = (r ==  1) ? hc : 0.f;
                float d0 = t0 - m0[n];
                float d1 = t1 - m1[n];
                float d2 = t2 - m2[n];
                a0 += d0 * d0;
                a1 += d1 * d1;
                a2 += d2 * d2;
            }
        }
        float S0 = blockReduce(a0, red);
        float S1 = blockReduce(a1, red);
        float S2 = blockReduce(a2, red);
        if (tid == 0) {
            float s = sqrtf(S0) + sqrtf(S1) + sqrtf(S2);
            atomicAdd(&g_acc[2], (double)(s * s));
        }
    }
}

// Kernel 3: combine into the scalar output.
__global__ void k_final(float* __restrict__ out) {
    double l3d  = g_acc[0] / 256.0;
    double lint = 0.005 * ((g_acc[1] + g_acc[2]) / 256.0);
    out[0] = (float)(l3d + lint);
}

extern "C" void kernel_launch(void* const* d_in, const int* in_sizes, int n_in,
                              void* d_out, int out_size) {
    const float* pred   = (const float*)d_in[0];
    const float* joints = (const float*)d_in[1];
    const float* mo     = (const float*)d_in[2];
    const float* j2d    = (const float*)d_in[3];
    float* out = (float*)d_out;

    k_init_l3d<<<1, 256>>>(pred, joints);
    k_main<<<dim3(NJ + NP, NB), 256>>>(mo, joints, j2d);
    k_final<<<1, 1>>>(out);
}